// round 5
// baseline (speedup 1.0000x reference)
#include <cuda_runtime.h>
#include <cuda_bf16.h>
#include <math.h>

#define NB 65536
#define HALF 32768
#define LH 64
#define GOALC 0.5f
#define MINPC (-1.2f)
#define UTHRESH 0.5f

// XLA / Eigen rational tanh approximation for f32 (matches reference lowering).
__device__ __forceinline__ float xla_tanh(float xin) {
    const float x = fminf(fmaxf(xin, -7.99881172180175781f), 7.99881172180175781f);
    const float x2 = __fmul_rn(x, x);
    float p = __fmaf_rn(x2, -2.76076847742355e-16f, 2.00018790482477e-13f);
    p = __fmaf_rn(x2, p, -8.60467152213735e-11f);
    p = __fmaf_rn(x2, p, 5.12229709037114e-08f);
    p = __fmaf_rn(x2, p, 1.48572235717979e-05f);
    p = __fmaf_rn(x2, p, 6.37261928875436e-04f);
    p = __fmaf_rn(x2, p, 4.89352455891786e-03f);
    p = __fmul_rn(x, p);
    float q = __fmaf_rn(x2, 1.19825839466702e-06f, 1.18534705686654e-04f);
    q = __fmaf_rn(x2, q, 2.26843463243900e-03f);
    q = __fmaf_rn(x2, q, 4.89352518554385e-03f);
    const float r = __fdiv_rn(p, q);
    return (fabsf(xin) < 0.0004f) ? xin : r;
}

// fp32 cos (|x| <= ~3.8), Cody-Waite with residual carry, ~1-1.5 ulp.
__device__ __forceinline__ float cos_cw(float x) {
    const float kf = rintf(__fmul_rn(x, 0.63661977236758134f));
    const int k = (int)kf;
    const float DP1 = 1.5703125f;
    const float DP2 = 4.837512969970703125e-4f;
    const float DP3 = 7.549789948768648e-8f;
    const float t  = __fmaf_rn(-kf, DP1, x);
    const float rh = __fmaf_rn(-kf, DP2, t);
    float rl = __fsub_rn(__fsub_rn(t, rh), __fmul_rn(kf, DP2));
    rl = __fmaf_rn(-kf, DP3, rl);
    const float z = __fmul_rn(rh, rh);

    float pc = __fmaf_rn(z, 2.443315711809948e-5f, -1.388731625493765e-3f);
    pc = __fmaf_rn(z, pc, 4.166664568298827e-2f);
    float c = __fmaf_rn(z, -0.5f, 1.0f);
    c = __fmaf_rn(__fmul_rn(z, z), pc, c);
    c = __fmaf_rn(-rl, rh, c);

    float ps = __fmaf_rn(z, -1.9515295891e-4f, 8.3321608736e-3f);
    ps = __fmaf_rn(z, ps, -1.6666654611e-1f);
    float s = __fmaf_rn(__fmul_rn(rh, z), ps, rl);
    s = __fadd_rn(rh, s);

    const int q = k & 3;
    float r = (q & 1) ? s : c;
    if (q == 1 || q == 2) r = -r;
    return r;
}

// Epilogue from pre-activation to new state (unchanged sequence from R3/R4).
__device__ __forceinline__ void epilogue(float pre, float pr, float vr,
                                         float& pn, float& vn, float& un, float& an) {
    an = xla_tanh(pre);
    un = (an <= UTHRESH) ? -1.0f : 1.0f;
    const float c = cos_cw(__fmul_rn(3.0f, pr));
    vn = __fsub_rn(__fadd_rn(vr, __fmul_rn(un, 0.0015f)), __fmul_rn(0.0025f, c));
    pn = __fadd_rn(pr, vn);
}

template<bool B1_ZERO>
__device__ __forceinline__ void run_pair(
    const float4* __restrict__ w, float bias2, int n,
    float& pA, float& vA, float& uA, float& aA,
    float& pB, float& vB, float& uB, float& aB)
{
    for (int t = 0; t < n; ++t) {
        const bool actA = (pA <= GOALC);
        const bool actB = (pB <= GOALC);
        if (!(actA || actB)) break;   // inactive is absorbing

        const bool rsA = (pA <= MINPC);
        const float prA = rsA ? MINPC : pA;
        const float vrA = rsA ? 0.0f : vA;
        const bool rsB = (pB <= MINPC);
        const float prB = rsB ? MINPC : pB;
        const float vrB = rsB ? 0.0f : vB;

        // Shared weight loads; 8 plain fma lanes per agent (16 total, huge ILP)
        float sa[8] = {0,0,0,0,0,0,0,0};
        float sb[8] = {0,0,0,0,0,0,0,0};
        #pragma unroll
        for (int j = 0; j < LH; ++j) {
            const float4 ww = w[j];
            float dA = __fmaf_rn(vrA, ww.y, __fmul_rn(prA, ww.x));
            float dB = __fmaf_rn(vrB, ww.y, __fmul_rn(prB, ww.x));
            if (!B1_ZERO) { dA = __fadd_rn(dA, ww.z); dB = __fadd_rn(dB, ww.z); }
            const float hA = fmaxf(dA, 0.0f);
            const float hB = fmaxf(dB, 0.0f);
            sa[j & 7] = __fmaf_rn(hA, ww.w, sa[j & 7]);
            sb[j & 7] = __fmaf_rn(hB, ww.w, sb[j & 7]);
        }
        // rn tree merge (pairwise) then + b2
        const float dotA =
            __fadd_rn(__fadd_rn(__fadd_rn(sa[0], sa[1]), __fadd_rn(sa[2], sa[3])),
                      __fadd_rn(__fadd_rn(sa[4], sa[5]), __fadd_rn(sa[6], sa[7])));
        const float dotB =
            __fadd_rn(__fadd_rn(__fadd_rn(sb[0], sb[1]), __fadd_rn(sb[2], sb[3])),
                      __fadd_rn(__fadd_rn(sb[4], sb[5]), __fadd_rn(sb[6], sb[7])));
        const float preA = __fadd_rn(dotA, bias2);
        const float preB = __fadd_rn(dotB, bias2);

        float pnA, vnA, unA, anA, pnB, vnB, unB, anB;
        epilogue(preA, prA, vrA, pnA, vnA, unA, anA);
        epilogue(preB, prB, vrB, pnB, vnB, unB, anB);

        if (actA) { pA = pnA; vA = vnA; uA = unA; aA = anA; }
        if (actB) { pB = pnB; vB = vnB; uB = unB; aB = anB; }
    }
}

__global__ __launch_bounds__(64, 8)
void mc_kernel(const float4* __restrict__ x,
               const float* __restrict__ W1,
               const float* __restrict__ b1,
               const float* __restrict__ W2,
               const float* __restrict__ b2,
               const int* __restrict__ n_steps,
               float4* __restrict__ out)
{
    __shared__ float4 w[LH];
    const int tid = threadIdx.x;
    const float b1v = b1[tid];
    w[tid] = make_float4(W1[tid], W1[LH + tid], b1v, W2[tid]);
    const int b1_zero = __syncthreads_and(__float_as_uint(b1v) == 0u);

    const float bias2 = b2[0];
    const int n = n_steps ? n_steps[0] : 64;

    const int iA = blockIdx.x * blockDim.x + tid;   // agents [0, 32768)
    const int iB = iA + HALF;                       // agents [32768, 65536)

    const float4 sA = x[iA];
    const float4 sB = x[iB];
    float pA = sA.x, vA = sA.y, uA = sA.z, aA = sA.w;
    float pB = sB.x, vB = sB.y, uB = sB.z, aB = sB.w;

    if (b1_zero) run_pair<true >(w, bias2, n, pA, vA, uA, aA, pB, vB, uB, aB);
    else         run_pair<false>(w, bias2, n, pA, vA, uA, aA, pB, vB, uB, aB);

    out[iA] = make_float4(pA, vA, uA, aA);
    out[iB] = make_float4(pB, vB, uB, aB);
}

extern "C" void kernel_launch(void* const* d_in, const int* in_sizes, int n_in,
                              void* d_out, int out_size) {
    const float* x  = (const float*)d_in[0];
    const float* W1 = (const float*)d_in[1];
    const float* b1 = (const float*)d_in[2];
    const float* W2 = (const float*)d_in[3];
    const float* b2 = (const float*)d_in[4];
    const int* ns   = (n_in >= 6) ? (const int*)d_in[5] : nullptr;

    mc_kernel<<<HALF / 64, 64>>>((const float4*)x, W1, b1, W2, b2, ns,
                                 (float4*)d_out);
}

// round 6
// speedup vs baseline: 4.1309x; 4.1309x over previous
#include <cuda_runtime.h>
#include <cuda_bf16.h>
#include <math.h>

#define NB 65536
#define HALF 32768
#define LH 64
#define GOALC 0.5f
#define MINPC (-1.2f)
#define UTHRESH 0.5f

// XLA / Eigen rational tanh approximation for f32 (matches reference lowering).
__device__ __forceinline__ float xla_tanh(float xin) {
    const float x = fminf(fmaxf(xin, -7.99881172180175781f), 7.99881172180175781f);
    const float x2 = __fmul_rn(x, x);
    float p = __fmaf_rn(x2, -2.76076847742355e-16f, 2.00018790482477e-13f);
    p = __fmaf_rn(x2, p, -8.60467152213735e-11f);
    p = __fmaf_rn(x2, p, 5.12229709037114e-08f);
    p = __fmaf_rn(x2, p, 1.48572235717979e-05f);
    p = __fmaf_rn(x2, p, 6.37261928875436e-04f);
    p = __fmaf_rn(x2, p, 4.89352455891786e-03f);
    p = __fmul_rn(x, p);
    float q = __fmaf_rn(x2, 1.19825839466702e-06f, 1.18534705686654e-04f);
    q = __fmaf_rn(x2, q, 2.26843463243900e-03f);
    q = __fmaf_rn(x2, q, 4.89352518554385e-03f);
    const float r = __fdiv_rn(p, q);
    return (fabsf(xin) < 0.0004f) ? xin : r;
}

// fp32 cos (|x| <= ~3.8), Cody-Waite with residual carry, ~1-1.5 ulp.
__device__ __forceinline__ float cos_cw(float x) {
    const float kf = rintf(__fmul_rn(x, 0.63661977236758134f));
    const int k = (int)kf;
    const float DP1 = 1.5703125f;
    const float DP2 = 4.837512969970703125e-4f;
    const float DP3 = 7.549789948768648e-8f;
    const float t  = __fmaf_rn(-kf, DP1, x);
    const float rh = __fmaf_rn(-kf, DP2, t);
    float rl = __fsub_rn(__fsub_rn(t, rh), __fmul_rn(kf, DP2));
    rl = __fmaf_rn(-kf, DP3, rl);
    const float z = __fmul_rn(rh, rh);

    float pc = __fmaf_rn(z, 2.443315711809948e-5f, -1.388731625493765e-3f);
    pc = __fmaf_rn(z, pc, 4.166664568298827e-2f);
    float c = __fmaf_rn(z, -0.5f, 1.0f);
    c = __fmaf_rn(__fmul_rn(z, z), pc, c);
    c = __fmaf_rn(-rl, rh, c);

    float ps = __fmaf_rn(z, -1.9515295891e-4f, 8.3321608736e-3f);
    ps = __fmaf_rn(z, ps, -1.6666654611e-1f);
    float s = __fmaf_rn(__fmul_rn(rh, z), ps, rl);
    s = __fadd_rn(rh, s);

    const int q = k & 3;
    float r = (q & 1) ? s : c;
    if (q == 1 || q == 2) r = -r;
    return r;
}

// Epilogue from pre-activation to new state (bit-identical to R5).
__device__ __forceinline__ void epilogue(float pre, float pr, float vr,
                                         float& pn, float& vn, float& un, float& an) {
    an = xla_tanh(pre);
    un = (an <= UTHRESH) ? -1.0f : 1.0f;
    const float c = cos_cw(__fmul_rn(3.0f, pr));
    vn = __fsub_rn(__fadd_rn(vr, __fmul_rn(un, 0.0015f)), __fmul_rn(0.0025f, c));
    pn = __fadd_rn(pr, vn);
}

template<bool B1_ZERO>
__device__ __forceinline__ void run_pair(
    const float4* __restrict__ w, float bias2, int n,
    float& pA, float& vA, float& uA, float& aA,
    float& pB, float& vB, float& uB, float& aB)
{
    for (int t = 0; t < n; ++t) {
        const bool actA = (pA <= GOALC);
        const bool actB = (pB <= GOALC);
        if (!(actA || actB)) break;   // inactive is absorbing

        const bool rsA = (pA <= MINPC);
        const float prA = rsA ? MINPC : pA;
        const float vrA = rsA ? 0.0f : vA;
        const bool rsB = (pB <= MINPC);
        const float prB = rsB ? MINPC : pB;
        const float vrB = rsB ? 0.0f : vB;

        // Shared weight loads; 8 plain fma lanes per agent (bit-identical to R5)
        float sa[8] = {0,0,0,0,0,0,0,0};
        float sb[8] = {0,0,0,0,0,0,0,0};
        #pragma unroll
        for (int j = 0; j < LH; ++j) {
            const float4 ww = w[j];
            float dA = __fmaf_rn(vrA, ww.y, __fmul_rn(prA, ww.x));
            float dB = __fmaf_rn(vrB, ww.y, __fmul_rn(prB, ww.x));
            if (!B1_ZERO) { dA = __fadd_rn(dA, ww.z); dB = __fadd_rn(dB, ww.z); }
            const float hA = fmaxf(dA, 0.0f);
            const float hB = fmaxf(dB, 0.0f);
            sa[j & 7] = __fmaf_rn(hA, ww.w, sa[j & 7]);
            sb[j & 7] = __fmaf_rn(hB, ww.w, sb[j & 7]);
        }
        const float dotA =
            __fadd_rn(__fadd_rn(__fadd_rn(sa[0], sa[1]), __fadd_rn(sa[2], sa[3])),
                      __fadd_rn(__fadd_rn(sa[4], sa[5]), __fadd_rn(sa[6], sa[7])));
        const float dotB =
            __fadd_rn(__fadd_rn(__fadd_rn(sb[0], sb[1]), __fadd_rn(sb[2], sb[3])),
                      __fadd_rn(__fadd_rn(sb[4], sb[5]), __fadd_rn(sb[6], sb[7])));
        const float preA = __fadd_rn(dotA, bias2);
        const float preB = __fadd_rn(dotB, bias2);

        float pnA, vnA, unA, anA, pnB, vnB, unB, anB;
        epilogue(preA, prA, vrA, pnA, vnA, unA, anA);
        epilogue(preB, prB, vrB, pnB, vnB, unB, anB);

        if (actA) { pA = pnA; vA = vnA; uA = unA; aA = anA; }
        if (actB) { pB = pnB; vB = vnB; uB = unB; aB = anB; }
    }
}

__global__ __launch_bounds__(64)   // no occupancy cap -> no spills (R4-proven)
void mc_kernel(const float4* __restrict__ x,
               const float* __restrict__ W1,
               const float* __restrict__ b1,
               const float* __restrict__ W2,
               const float* __restrict__ b2,
               const int* __restrict__ n_steps,
               float4* __restrict__ out)
{
    __shared__ float4 w[LH];
    const int tid = threadIdx.x;
    const float b1v = b1[tid];
    w[tid] = make_float4(W1[tid], W1[LH + tid], b1v, W2[tid]);
    const int b1_zero = __syncthreads_and(__float_as_uint(b1v) == 0u);

    const float bias2 = b2[0];
    const int n = n_steps ? n_steps[0] : 64;

    const int iA = blockIdx.x * blockDim.x + tid;   // agents [0, 32768)
    const int iB = iA + HALF;                       // agents [32768, 65536)

    const float4 sA = x[iA];
    const float4 sB = x[iB];
    float pA = sA.x, vA = sA.y, uA = sA.z, aA = sA.w;
    float pB = sB.x, vB = sB.y, uB = sB.z, aB = sB.w;

    if (b1_zero) run_pair<true >(w, bias2, n, pA, vA, uA, aA, pB, vB, uB, aB);
    else         run_pair<false>(w, bias2, n, pA, vA, uA, aA, pB, vB, uB, aB);

    out[iA] = make_float4(pA, vA, uA, aA);
    out[iB] = make_float4(pB, vB, uB, aB);
}

extern "C" void kernel_launch(void* const* d_in, const int* in_sizes, int n_in,
                              void* d_out, int out_size) {
    const float* x  = (const float*)d_in[0];
    const float* W1 = (const float*)d_in[1];
    const float* b1 = (const float*)d_in[2];
    const float* W2 = (const float*)d_in[3];
    const float* b2 = (const float*)d_in[4];
    const int* ns   = (n_in >= 6) ? (const int*)d_in[5] : nullptr;

    mc_kernel<<<HALF / 64, 64>>>((const float4*)x, W1, b1, W2, b2, ns,
                                 (float4*)d_out);
}